// round 1
// baseline (speedup 1.0000x reference)
#include <cuda_runtime.h>

// out = LeakyReLU( D^-1 * (A @ (X @ W^T)) + b )
// B=32, N=1024, FIN=FOUT=128
//
// Kernel 1: g_xw[b,n,o] = sum_f X[b,n,f] * W[o,f]           (M=32768,N=128,K=128)
// Kernel 2: out[b,n,o]  = leaky( (sum_m A[b,n,m]*g_xw[b,m,o]) / deg[b,n] + bias[o] )
//           deg fused from the A tiles streamed by the GEMM itself (A read once).

#define NEG_SLOPE 0.01f

// 16 MB scratch for XW (alloc-free rule: __device__ global)
__device__ float g_xw[32u * 1024u * 128u];

__device__ __forceinline__ unsigned long long pack2(float lo, float hi) {
    unsigned long long r;
    asm("mov.b64 %0, {%1, %2};" : "=l"(r)
        : "r"(__float_as_uint(lo)), "r"(__float_as_uint(hi)));
    return r;
}
__device__ __forceinline__ void fma2(unsigned long long& d,
                                     unsigned long long a,
                                     unsigned long long b) {
    asm("fma.rn.f32x2 %0, %1, %2, %0;" : "+l"(d) : "l"(a), "l"(b));
}
__device__ __forceinline__ void unpack2(unsigned long long v, float& lo, float& hi) {
    unsigned int a, b;
    asm("mov.b64 {%0, %1}, %2;" : "=r"(a), "=r"(b) : "l"(v));
    lo = __uint_as_float(a);
    hi = __uint_as_float(b);
}

// ---------------------------------------------------------------------------
// Kernel 1: XW = X @ W^T   (rows m = flattened b*1024+n)
// BM=64, BN=128, BK=32, 256 threads, 8x4 outputs/thread (as 8x2 f32x2 pairs)
// ---------------------------------------------------------------------------
__global__ __launch_bounds__(256) void k_xw(const float* __restrict__ X,
                                            const float* __restrict__ W) {
    __shared__ float Xs[64][36];    // padded stride 36: conflict-free STS.128
    __shared__ float Ws[32][128];   // Ws[k][o]

    const int tid = threadIdx.x;
    const int m0  = blockIdx.x * 64;
    const int tr  = tid >> 5;        // 0..7  (row group)
    const int tc  = tid & 31;        // 0..31 (col group, 4 cols each)

    const int lrow = tid >> 2;       // 0..63 : A-tile row this thread loads
    const int lc4  = (tid & 3) * 2;  // float4 col of first of 2 loads

    const int wo  = tid & 127;       // W row (output feature)
    const int wkh = tid >> 7;        // 0/1 : which 16-wide k half

    unsigned long long acc[8][2];
#pragma unroll
    for (int i = 0; i < 8; i++) { acc[i][0] = 0ull; acc[i][1] = 0ull; }

    for (int kt = 0; kt < 128; kt += 32) {
        // global loads first (overlap with previous tile's consumers draining)
        const float4* xg = (const float4*)(X + (long long)(m0 + lrow) * 128 + kt);
        float4 xv0 = xg[lc4];
        float4 xv1 = xg[lc4 + 1];

        const float4* wg = (const float4*)(W + wo * 128 + kt + wkh * 16);
        float4 wv0 = wg[0], wv1 = wg[1], wv2 = wg[2], wv3 = wg[3];

        __syncthreads();
        *(float4*)&Xs[lrow][lc4 * 4]     = xv0;
        *(float4*)&Xs[lrow][lc4 * 4 + 4] = xv1;
        {
            int kb = wkh * 16;
            Ws[kb + 0][wo] = wv0.x; Ws[kb + 1][wo] = wv0.y; Ws[kb + 2][wo] = wv0.z; Ws[kb + 3][wo] = wv0.w;
            Ws[kb + 4][wo] = wv1.x; Ws[kb + 5][wo] = wv1.y; Ws[kb + 6][wo] = wv1.z; Ws[kb + 7][wo] = wv1.w;
            Ws[kb + 8][wo] = wv2.x; Ws[kb + 9][wo] = wv2.y; Ws[kb +10][wo] = wv2.z; Ws[kb +11][wo] = wv2.w;
            Ws[kb +12][wo] = wv3.x; Ws[kb +13][wo] = wv3.y; Ws[kb +14][wo] = wv3.z; Ws[kb +15][wo] = wv3.w;
        }
        __syncthreads();

#pragma unroll
        for (int k4 = 0; k4 < 32; k4 += 4) {
            float ar[8][4];
#pragma unroll
            for (int i = 0; i < 8; i++) {
                float4 t = *(const float4*)&Xs[tr * 8 + i][k4];  // broadcast
                ar[i][0] = t.x; ar[i][1] = t.y; ar[i][2] = t.z; ar[i][3] = t.w;
            }
#pragma unroll
            for (int kk = 0; kk < 4; kk++) {
                float4 b4 = *(const float4*)&Ws[k4 + kk][tc * 4];
                unsigned long long b01 = pack2(b4.x, b4.y);
                unsigned long long b23 = pack2(b4.z, b4.w);
#pragma unroll
                for (int i = 0; i < 8; i++) {
                    unsigned long long aa = pack2(ar[i][kk], ar[i][kk]);
                    fma2(acc[i][0], aa, b01);
                    fma2(acc[i][1], aa, b23);
                }
            }
        }
    }

#pragma unroll
    for (int i = 0; i < 8; i++) {
        float4 v;
        unpack2(acc[i][0], v.x, v.y);
        unpack2(acc[i][1], v.z, v.w);
        *(float4*)&g_xw[(long long)(m0 + tr * 8 + i) * 128 + tc * 4] = v;
    }
}

// ---------------------------------------------------------------------------
// Kernel 2: per batch  C = A[1024,1024] @ XW[1024,128]; fused deg / bias / LeakyReLU
// Same tiling. deg accumulated from the A values each thread loads (one row each).
// ---------------------------------------------------------------------------
__global__ __launch_bounds__(256) void k_agg(const float* __restrict__ Aadj,
                                             const float* __restrict__ bias,
                                             float* __restrict__ out) {
    __shared__ float As[64][36];
    __shared__ float Bs[32][128];
    __shared__ float degs[64];

    const int tid = threadIdx.x;
    const int bz  = blockIdx.y;               // batch
    const int m0  = blockIdx.x * 64;          // row tile
    const float* Ab  = Aadj + (long long)bz * 1024 * 1024;
    const float* XWb = g_xw + (long long)bz * 1024 * 128;

    const int tr = tid >> 5;
    const int tc = tid & 31;
    const int lrow = tid >> 2;
    const int lc4  = (tid & 3) * 2;

    unsigned long long acc[8][2];
#pragma unroll
    for (int i = 0; i < 8; i++) { acc[i][0] = 0ull; acc[i][1] = 0ull; }
    float deg = 0.0f;

    for (int kt = 0; kt < 1024; kt += 32) {
        const float4* ag = (const float4*)(Ab + (long long)(m0 + lrow) * 1024 + kt);
        float4 av0 = ag[lc4];
        float4 av1 = ag[lc4 + 1];
        deg += (av0.x + av0.y) + (av0.z + av0.w) + (av1.x + av1.y) + (av1.z + av1.w);

        const float4* bg = (const float4*)(XWb + kt * 128);  // 32x128 contiguous
        float4 bv0 = bg[tid];
        float4 bv1 = bg[tid + 256];
        float4 bv2 = bg[tid + 512];
        float4 bv3 = bg[tid + 768];

        __syncthreads();
        *(float4*)&As[lrow][lc4 * 4]     = av0;
        *(float4*)&As[lrow][lc4 * 4 + 4] = av1;
        ((float4*)Bs)[tid]       = bv0;
        ((float4*)Bs)[tid + 256] = bv1;
        ((float4*)Bs)[tid + 512] = bv2;
        ((float4*)Bs)[tid + 768] = bv3;
        __syncthreads();

#pragma unroll
        for (int k4 = 0; k4 < 32; k4 += 4) {
            float ar[8][4];
#pragma unroll
            for (int i = 0; i < 8; i++) {
                float4 t = *(const float4*)&As[tr * 8 + i][k4];  // broadcast
                ar[i][0] = t.x; ar[i][1] = t.y; ar[i][2] = t.z; ar[i][3] = t.w;
            }
#pragma unroll
            for (int kk = 0; kk < 4; kk++) {
                float4 b4 = *(const float4*)&Bs[k4 + kk][tc * 4];
                unsigned long long b01 = pack2(b4.x, b4.y);
                unsigned long long b23 = pack2(b4.z, b4.w);
#pragma unroll
                for (int i = 0; i < 8; i++) {
                    unsigned long long aa = pack2(ar[i][kk], ar[i][kk]);
                    fma2(acc[i][0], aa, b01);
                    fma2(acc[i][1], aa, b23);
                }
            }
        }
    }

    // deg: 4 threads (consecutive lanes) share a row -> butterfly within warp
    deg += __shfl_xor_sync(0xffffffffu, deg, 1);
    deg += __shfl_xor_sync(0xffffffffu, deg, 2);
    if ((tid & 3) == 0) degs[lrow] = deg;
    __syncthreads();

    float4 bvec = *(const float4*)&bias[tc * 4];

#pragma unroll
    for (int i = 0; i < 8; i++) {
        int row = tr * 8 + i;
        float inv = 1.0f / degs[row];
        float4 v;
        unpack2(acc[i][0], v.x, v.y);
        unpack2(acc[i][1], v.z, v.w);
        v.x = v.x * inv + bvec.x;
        v.y = v.y * inv + bvec.y;
        v.z = v.z * inv + bvec.z;
        v.w = v.w * inv + bvec.w;
        v.x = (v.x >= 0.0f) ? v.x : NEG_SLOPE * v.x;
        v.y = (v.y >= 0.0f) ? v.y : NEG_SLOPE * v.y;
        v.z = (v.z >= 0.0f) ? v.z : NEG_SLOPE * v.z;
        v.w = (v.w >= 0.0f) ? v.w : NEG_SLOPE * v.w;
        *(float4*)&out[((long long)bz * 1024 + m0 + row) * 128 + tc * 4] = v;
    }
}

extern "C" void kernel_launch(void* const* d_in, const int* in_sizes, int n_in,
                              void* d_out, int out_size) {
    const float* node = (const float*)d_in[0];  // [32,1024,128]
    const float* adj  = (const float*)d_in[1];  // [32,1024,1024]
    const float* W    = (const float*)d_in[2];  // [128,128]
    const float* bias = (const float*)d_in[3];  // [128]
    float* out = (float*)d_out;                 // [32,1024,128]

    // XW = X @ W^T : 32768 rows / 64 per block
    k_xw<<<512, 256>>>(node, W);

    // out = leaky( (A @ XW) / deg + b ) : 16 row-tiles x 32 batches
    dim3 grid(16, 32);
    k_agg<<<grid, 256>>>(adj, bias, out);
}

// round 3
// speedup vs baseline: 2.6092x; 2.6092x over previous
#include <cuda_runtime.h>
#include <cstdint>

// out = LeakyReLU( D^-1 * (A @ (X @ W^T)) + b ),  B=32, N=1024, F=128
// No 'a'-suffix ISA available (harness targets compute_103) -> use base-ISA
// tensor path: mma.sync m16n8k8 tf32 + cp.async double buffering.
//
// k_xw  : XW[m][o] = sum_f X[m,f] * W[o,f]     (Markidis 3-term tf32 ~ fp32 acc)
// k_main: C[n][o]  = sum_m A[n,m] * XW[m][o]   (single tf32)
//         deg[n]   = sum_m A[n,m]  fused as extra N=8 mma vs all-ones B frag
//         epilogue: leaky(C/deg + bias)

#define NEG_SLOPE 0.01f

__device__ float g_xw[32u * 1024u * 128u];  // [32768][128] scratch (16 MB)

// ---------------- helpers ----------------
__device__ __forceinline__ uint32_t su32(const void* p) {
    uint32_t r;
    asm("{\n\t.reg .u64 t;\n\tcvta.to.shared.u64 t, %1;\n\tcvt.u32.u64 %0, t;\n\t}"
        : "=r"(r) : "l"(p));
    return r;
}
__device__ __forceinline__ void cp16(uint32_t dst, const void* src) {
    asm volatile("cp.async.cg.shared.global [%0], [%1], 16;" :: "r"(dst), "l"(src));
}
__device__ __forceinline__ void cp_commit() {
    asm volatile("cp.async.commit_group;" ::: "memory");
}
template <int N>
__device__ __forceinline__ void cp_wait() {
    asm volatile("cp.async.wait_group %0;" :: "n"(N) : "memory");
}
__device__ __forceinline__ uint32_t tf32_rna(float x) {
    uint32_t r;
    asm("cvt.rna.tf32.f32 %0, %1;" : "=r"(r) : "f"(x));
    return r;
}
__device__ __forceinline__ void mma8(float* c, const uint32_t* a, const uint32_t* b) {
    asm volatile(
        "mma.sync.aligned.m16n8k8.row.col.f32.tf32.tf32.f32 "
        "{%0,%1,%2,%3}, {%4,%5,%6,%7}, {%8,%9}, {%0,%1,%2,%3};"
        : "+f"(c[0]), "+f"(c[1]), "+f"(c[2]), "+f"(c[3])
        : "r"(a[0]), "r"(a[1]), "r"(a[2]), "r"(a[3]), "r"(b[0]), "r"(b[1]));
}
__device__ __forceinline__ float leaky(float v) {
    return (v >= 0.0f) ? v : NEG_SLOPE * v;
}

#define AP 36   // A/X smem row pad (floats): bank = 4g+tig -> bijective per lane
#define BP 132  // B smem row pad

// =====================================================================
// k_xw: XW = X @ W^T.  grid=256 (m-tiles of 128), 256 threads.
// smem: Ws[128][BP] (W[o][f], whole 128x128) | Xs[2][128][AP] (k-tiles of 32)
// Markidis: x=xh+xl, w=wh+wl; acc += xh*wh + xh*wl + xl*wh  (~fp32 accuracy)
// =====================================================================
#define XW_SMEM ((128 * BP + 2 * 128 * AP) * 4)

__global__ __launch_bounds__(256, 2) void k_xw(const float* __restrict__ X,
                                               const float* __restrict__ W) {
    extern __shared__ float sm[];
    float* Ws = sm;                 // 128*BP floats
    float* Xs = sm + 128 * BP;      // 2*128*AP floats
    const uint32_t ws_a = su32(Ws), xs_a = su32(Xs);

    const int tid = threadIdx.x, lane = tid & 31, wid = tid >> 5;
    const int g = lane >> 2, tig = lane & 3;
    const int wr = wid & 3, wc = wid >> 2;
    const int m0 = blockIdx.x * 128;

    // async-load whole W [128][128] -> Ws[o][f], 16 float4/thread (group 0)
#pragma unroll
    for (int i = 0; i < 16; i++) {
        int idx = tid + i * 256;           // 0..4095 float4
        int o = idx >> 5, f4 = idx & 31;
        cp16(ws_a + (uint32_t)(o * BP + f4 * 4) * 4, W + o * 128 + f4 * 4);
    }
    cp_commit();

    const int lr = tid >> 3, lc4 = tid & 7;
    auto loadX = [&](int buf, int kt) {
#pragma unroll
        for (int i = 0; i < 4; i++) {
            int row = lr + i * 32;
            cp16(xs_a + (uint32_t)((buf * 128 + row) * AP + lc4 * 4) * 4,
                 X + (size_t)(m0 + row) * 128 + kt * 32 + lc4 * 4);
        }
        cp_commit();
    };
    loadX(0, 0);

    float acc[2][8][4];
#pragma unroll
    for (int mi = 0; mi < 2; mi++)
#pragma unroll
        for (int ni = 0; ni < 8; ni++)
#pragma unroll
            for (int q = 0; q < 4; q++) acc[mi][ni][q] = 0.0f;

    for (int kt = 0; kt < 4; kt++) {
        if (kt < 3) { loadX((kt + 1) & 1, kt + 1); cp_wait<1>(); }
        else cp_wait<0>();
        __syncthreads();
        const int buf = kt & 1;
#pragma unroll
        for (int k0 = 0; k0 < 32; k0 += 8) {
            uint32_t ah[2][4], al[2][4];
#pragma unroll
            for (int mi = 0; mi < 2; mi++) {
                int row = wr * 32 + mi * 16 + g;
#pragma unroll
                for (int q = 0; q < 4; q++) {
                    int rr = row + (q & 1) * 8, cc = k0 + tig + (q >> 1) * 4;
                    float x = Xs[(buf * 128 + rr) * AP + cc];
                    uint32_t h = tf32_rna(x);
                    ah[mi][q] = h;
                    al[mi][q] = __float_as_uint(x - __uint_as_float(h));
                }
            }
#pragma unroll
            for (int ni = 0; ni < 8; ni++) {
                int o = wc * 64 + ni * 8 + g;
                uint32_t bh[2], bl[2];
#pragma unroll
                for (int q = 0; q < 2; q++) {
                    float w = Ws[o * BP + kt * 32 + k0 + tig + q * 4];
                    uint32_t h = tf32_rna(w);
                    bh[q] = h;
                    bl[q] = __float_as_uint(w - __uint_as_float(h));
                }
#pragma unroll
                for (int mi = 0; mi < 2; mi++) {
                    mma8(acc[mi][ni], ah[mi], bh);
                    mma8(acc[mi][ni], ah[mi], bl);
                    mma8(acc[mi][ni], al[mi], bh);
                }
            }
        }
        __syncthreads();
    }

    // store XW[m][o]
#pragma unroll
    for (int mi = 0; mi < 2; mi++) {
        int row = m0 + wr * 32 + mi * 16 + g;
#pragma unroll
        for (int ni = 0; ni < 8; ni++) {
            int col = wc * 64 + ni * 8 + tig * 2;
            *(float2*)(g_xw + (size_t)row * 128 + col) =
                make_float2(acc[mi][ni][0], acc[mi][ni][1]);
            *(float2*)(g_xw + (size_t)(row + 8) * 128 + col) =
                make_float2(acc[mi][ni][2], acc[mi][ni][3]);
        }
    }
}

// =====================================================================
// k_main: per batch C = A[1024,1024] @ XW[1024,128]; deg fused via ones-mma.
// grid (8,32), 256 threads, warps 4x2; BK=32, cp.async double buffer.
// smem: As[2][128][AP] | Bs[2][32][BP] | degs[128]
// =====================================================================
#define MAIN_SMEM ((2 * 128 * AP + 2 * 32 * BP + 128) * 4)

__global__ __launch_bounds__(256, 2) void k_main(const float* __restrict__ A,
                                                 const float* __restrict__ bias,
                                                 float* __restrict__ out) {
    extern __shared__ float sm[];
    float* As = sm;                                  // 2*128*AP
    float* Bs = sm + 2 * 128 * AP;                   // 2*32*BP
    float* degs = sm + 2 * 128 * AP + 2 * 32 * BP;   // 128
    const uint32_t as_a = su32(As), bs_a = su32(Bs);

    const int tid = threadIdx.x, lane = tid & 31, wid = tid >> 5;
    const int g = lane >> 2, tig = lane & 3;
    const int wr = wid & 3, wc = wid >> 2;
    const int m0 = blockIdx.x * 128, bz = blockIdx.y;
    const float* Ab = A + (size_t)bz * 1024 * 1024;
    const float* Bb = g_xw + (size_t)bz * 1024 * 128;

    const int lr = tid >> 3, lc4 = tid & 7;    // A: 128 rows x 8 f4
    const int br = tid >> 5, bc4 = tid & 31;   // B: 32 rows x 32 f4

    auto loadT = [&](int buf, int s) {
#pragma unroll
        for (int i = 0; i < 4; i++) {
            int row = lr + i * 32;
            cp16(as_a + (uint32_t)((buf * 128 + row) * AP + lc4 * 4) * 4,
                 Ab + (size_t)(m0 + row) * 1024 + s * 32 + lc4 * 4);
        }
#pragma unroll
        for (int i = 0; i < 4; i++) {
            int row = br + i * 8;
            cp16(bs_a + (uint32_t)((buf * 32 + row) * BP + bc4 * 4) * 4,
                 Bb + (size_t)(s * 32 + row) * 128 + bc4 * 4);
        }
        cp_commit();
    };

    float acc[2][8][4];
#pragma unroll
    for (int mi = 0; mi < 2; mi++)
#pragma unroll
        for (int ni = 0; ni < 8; ni++)
#pragma unroll
            for (int q = 0; q < 4; q++) acc[mi][ni][q] = 0.0f;
    float dacc[2][4] = {{0, 0, 0, 0}, {0, 0, 0, 0}};
    const uint32_t ones[2] = {0x3F800000u, 0x3F800000u};

    loadT(0, 0);

    for (int s = 0; s < 32; s++) {
        if (s < 31) { loadT((s + 1) & 1, s + 1); cp_wait<1>(); }
        else cp_wait<0>();
        __syncthreads();
        const int buf = s & 1;
#pragma unroll
        for (int k0 = 0; k0 < 32; k0 += 8) {
            uint32_t a[2][4];
#pragma unroll
            for (int mi = 0; mi < 2; mi++) {
                int row = wr * 32 + mi * 16 + g;
#pragma unroll
                for (int q = 0; q < 4; q++) {
                    int rr = row + (q & 1) * 8, cc = k0 + tig + (q >> 1) * 4;
                    a[mi][q] = __float_as_uint(As[(buf * 128 + rr) * AP + cc]);
                }
            }
#pragma unroll
            for (int ni = 0; ni < 8; ni++) {
                int n = wc * 64 + ni * 8 + g;
                uint32_t b[2];
                b[0] = __float_as_uint(Bs[(buf * 32 + k0 + tig) * BP + n]);
                b[1] = __float_as_uint(Bs[(buf * 32 + k0 + tig + 4) * BP + n]);
                mma8(acc[0][ni], a[0], b);
                mma8(acc[1][ni], a[1], b);
            }
            if (wc == 0) {  // fused degree: row-sum via all-ones B fragment
                mma8(dacc[0], a[0], ones);
                mma8(dacc[1], a[1], ones);
            }
        }
        __syncthreads();
    }

    if (wc == 0 && tig == 0) {
        degs[wr * 32 + g]      = dacc[0][0];
        degs[wr * 32 + g + 8]  = dacc[0][2];
        degs[wr * 32 + g + 16] = dacc[1][0];
        degs[wr * 32 + g + 24] = dacc[1][2];
    }
    __syncthreads();

    float inv[2][2];
#pragma unroll
    for (int mi = 0; mi < 2; mi++) {
        inv[mi][0] = 1.0f / degs[wr * 32 + mi * 16 + g];
        inv[mi][1] = 1.0f / degs[wr * 32 + mi * 16 + g + 8];
    }

#pragma unroll
    for (int ni = 0; ni < 8; ni++) {
        int col = wc * 64 + ni * 8 + tig * 2;
        float2 bv = *(const float2*)(bias + col);
#pragma unroll
        for (int mi = 0; mi < 2; mi++) {
            int row = m0 + wr * 32 + mi * 16 + g;
            float2 v0, v1;
            v0.x = leaky(fmaf(acc[mi][ni][0], inv[mi][0], bv.x));
            v0.y = leaky(fmaf(acc[mi][ni][1], inv[mi][0], bv.y));
            v1.x = leaky(fmaf(acc[mi][ni][2], inv[mi][1], bv.x));
            v1.y = leaky(fmaf(acc[mi][ni][3], inv[mi][1], bv.y));
            *(float2*)(out + ((size_t)bz * 1024 + row) * 128 + col) = v0;
            *(float2*)(out + ((size_t)bz * 1024 + row + 8) * 128 + col) = v1;
        }
    }
}

// ---------------- host ----------------
extern "C" void kernel_launch(void* const* d_in, const int* in_sizes, int n_in,
                              void* d_out, int out_size) {
    const float* X    = (const float*)d_in[0];  // [32,1024,128]
    const float* adj  = (const float*)d_in[1];  // [32,1024,1024]
    const float* W    = (const float*)d_in[2];  // [128,128]
    const float* bias = (const float*)d_in[3];  // [128]
    float* out = (float*)d_out;                 // [32,1024,128]

    static int inited = 0;
    if (!inited) {
        cudaFuncSetAttribute(k_xw, cudaFuncAttributeMaxDynamicSharedMemorySize, XW_SMEM);
        cudaFuncSetAttribute(k_main, cudaFuncAttributeMaxDynamicSharedMemorySize, MAIN_SMEM);
        inited = 1;
    }

    k_xw<<<256, 256, XW_SMEM>>>(X, W);
    k_main<<<dim3(8, 32), 256, MAIN_SMEM>>>(adj, bias, out);
}